// round 8
// baseline (speedup 1.0000x reference)
#include <cuda_runtime.h>
#include <cstdint>

// Problem constants (fixed by the reference setup)
#define BB 32
#define SS 32
#define AA 512
#define VOCAB 32000
#define SENTINEL 0x7FFFFFFF
#define NBKT 128                 // bucket = m >> 8, sentinel bucket 127

// Persistent-kernel geometry
#define GRID 256                 // <= 2 blocks/SM on 148 SMs -> all resident
#define TPB  512
#define NCHUNK 8
#define ROWS_PER_CHUNK 128       // 1024 rows / 8
#define F4_TOTAL (BB * SS * VOCAB / 4)        // 8,192,000
#define F4_PER_CHUNK (F4_TOTAL / NCHUNK)      // 1,024,000 (=128 rows * 8000)
#define F4_PER_BLOCK (F4_PER_CHUNK / GRID)    // 4000
#define TASKS_PER_BLOCK (ROWS_PER_CHUNK * AA / GRID)  // 256

// Scratch + synchronization state (zero-init at load; reset every launch)
__device__ int g_sorted[BB * AA];       // per-batch bucket-sorted (m<<9)|a
__device__ int g_copy_done[NCHUNK];     // blocks finished copying chunk c
__device__ int g_sort_done;             // batches sorted (target 32)
__device__ int g_fin;                   // blocks finished everything

// ---------------------------------------------------------------------------
// Per-batch counting sort into g_sorted (executed by blocks 0..31 only).
// 128 buckets of m>>8 -> 1KB vocab windows: DRAM-row-friendly atomic order.
// ---------------------------------------------------------------------------
__device__ __forceinline__ void sort_batch(const int* __restrict__ seq,
                                           const int* __restrict__ tbl,
                                           int b, int tid) {
    __shared__ int hist[NBKT];
    __shared__ int offs[NBKT];

    if (tid < NBKT) hist[tid] = 0;
    __syncthreads();

    int m = tbl[seq[(b << 9) + tid]];
    int bkt    = (m == 1) ? (NBKT - 1) : (m >> 8);
    int packed = (m == 1) ? SENTINEL   : ((m << 9) | tid);
    int rank   = atomicAdd(&hist[bkt], 1);
    __syncthreads();

    if (tid < 32) {   // exclusive scan of 128 counts: 4/lane + shfl
        int c0 = hist[tid * 4], c1 = hist[tid * 4 + 1];
        int c2 = hist[tid * 4 + 2], c3 = hist[tid * 4 + 3];
        int lsum = c0 + c1 + c2 + c3;
        int pre = lsum;
        #pragma unroll
        for (int d = 1; d < 32; d <<= 1) {
            int n = __shfl_up_sync(0xFFFFFFFF, pre, d);
            if (tid >= d) pre += n;
        }
        pre -= lsum;
        offs[tid * 4]     = pre;
        offs[tid * 4 + 1] = pre + c0;
        offs[tid * 4 + 2] = pre + c0 + c1;
        offs[tid * 4 + 3] = pre + c0 + c1 + c2;
    }
    __syncthreads();

    g_sorted[(b << 9) + offs[bkt] + rank] = packed;
    __threadfence();
    __syncthreads();
    if (tid == 0) atomicAdd(&g_sort_done, 1);
}

// ---------------------------------------------------------------------------
// Persistent pipelined kernel: copy chunk c, then scatter chunk c-1 while
// other blocks copy chunk c. Software chunk barriers; all blocks resident.
// ---------------------------------------------------------------------------
__global__ void __launch_bounds__(TPB, 2)
pg_persist_kernel(const float4* __restrict__ src,
                  const float*  __restrict__ att,
                  const int*    __restrict__ seq,
                  const int*    __restrict__ tbl,
                  float*        __restrict__ out) {
    int bid = blockIdx.x, tid = threadIdx.x;
    float4* dst = (float4*)out;

    if (bid < BB) sort_batch(seq, tbl, bid, tid);

    for (int c = 0; c <= NCHUNK; c++) {
        // ---- copy own share of chunk c ----
        if (c < NCHUNK) {
            size_t base = (size_t)c * F4_PER_CHUNK + (size_t)bid * F4_PER_BLOCK;
            #pragma unroll
            for (int j = 0; j < 8; j++) {
                int off = j * TPB + tid;
                if (off < F4_PER_BLOCK)
                    __stcs(dst + base + off, __ldcs(src + base + off));
            }
            __threadfence();
            __syncthreads();
            if (tid == 0) atomicAdd(&g_copy_done[c], 1);
        }

        // ---- scatter chunk c-1 (fully copied once its counter hits GRID) ----
        if (c >= 1) {
            int sc = c - 1;
            if (tid == 0) {
                volatile int* cd = g_copy_done;
                volatile int* sd = &g_sort_done;
                while (cd[sc] < GRID || *sd < BB) { }
                __threadfence();
            }
            __syncthreads();
            if (tid < TASKS_PER_BLOCK) {
                int t    = bid * TASKS_PER_BLOCK + tid;       // 0..65535 chunk task
                int row  = sc * ROWS_PER_CHUNK + (t >> 9);    // bs row
                int rank = t & (AA - 1);
                int b    = row >> 5;
                if (rank == 0)
                    out[(size_t)row * VOCAB + 1] = 0.0f;      // out[:,:,1]=0 (safe: m==1 never scattered)
                int p = g_sorted[(b << 9) + rank];
                if (p != SENTINEL) {
                    int mm = p >> 9;
                    int a  = p & (AA - 1);
                    float v = att[(size_t)row * AA + a];
                    atomicMax((int*)out + (size_t)row * VOCAB + mm,
                              __float_as_int(v));
                }
            }
        }
    }

    // ---- last block to finish resets counters for the next graph replay ----
    __syncthreads();
    if (tid == 0) {
        __threadfence();
        int old = atomicAdd(&g_fin, 1);
        if (old == GRID - 1) {
            #pragma unroll
            for (int c = 0; c < NCHUNK; c++) g_copy_done[c] = 0;
            g_sort_done = 0;
            __threadfence();
            g_fin = 0;
            __threadfence();
        }
    }
}

// ---------------------------------------------------------------------------
// Launch
// Inputs (metadata order):
//   d_in[0] decoder_outputs  f32 [B,S,VOCAB]
//   d_in[1] attention_scores f32 [B,S,A]
//   d_in[2] input_sequence   i32 [B,A]
//   d_in[3] repeat_idx       i32 [S,1]   (unused)
//   d_in[4] repeat_idx2      i32 [B,1]   (unused)
//   d_in[5] convert_table    i32 [SRC_VOCAB]
// Output: f32 [B,S,VOCAB]
// ---------------------------------------------------------------------------
extern "C" void kernel_launch(void* const* d_in, const int* in_sizes, int n_in,
                              void* d_out, int out_size) {
    const float4* dec = (const float4*)d_in[0];
    const float*  att = (const float*)d_in[1];
    const int*    seq = (const int*)d_in[2];
    const int*    tbl = (const int*)d_in[5];
    float*        out = (float*)d_out;

    pg_persist_kernel<<<GRID, TPB>>>(dec, att, seq, tbl, out);
}

// round 9
// speedup vs baseline: 1.6453x; 1.6453x over previous
#include <cuda_runtime.h>
#include <cstdint>

// Problem constants (fixed by the reference setup)
#define BB 32
#define SS 32
#define AA 512
#define VOCAB 32000
#define SENTINEL 0x7FFFFFFF
#define NBKT 128            // bucket = m >> 8 (0..124), sentinel bucket 127

// Per-batch (m,a) pairs packed as (m<<9)|a, bucket-ordered by m>>8.
__device__ int g_sorted[BB * AA];   // 64 KB, L2-resident

// ---------------------------------------------------------------------------
// Kernel 1: streaming copy with the per-batch counting sort folded into
// blocks 0..31 as a prologue. The copy is DRAM-bound with issue slots and
// waves to spare, so the 32 sort prologues (latency-bound gathers + smem
// sort) hide completely under the 262 MB stream — the standalone 5us sort
// launch disappears.
// 2000 blocks x 512 threads x 8 float4 = 8,192,000 float4s.
// ---------------------------------------------------------------------------
__global__ void __launch_bounds__(512)
pg_copy_sort_kernel(const float4* __restrict__ src,
                    float4*       __restrict__ dst,
                    const int*    __restrict__ seq,
                    const int*    __restrict__ tbl) {
    __shared__ int hist[NBKT];
    __shared__ int offs[NBKT];

    int bid = blockIdx.x;
    int tid = threadIdx.x;

    // ---- sort prologue: blocks 0..31 counting-sort their batch ----
    if (bid < BB) {
        if (tid < NBKT) hist[tid] = 0;
        __syncthreads();

        int m = tbl[seq[(bid << 9) + tid]];
        int bkt    = (m == 1) ? (NBKT - 1) : (m >> 8);
        int packed = (m == 1) ? SENTINEL   : ((m << 9) | tid);
        int rank   = atomicAdd(&hist[bkt], 1);
        __syncthreads();

        // Exclusive scan of 128 bucket counts by warp 0 (4/lane + shfl).
        if (tid < 32) {
            int c0 = hist[tid * 4 + 0], c1 = hist[tid * 4 + 1];
            int c2 = hist[tid * 4 + 2], c3 = hist[tid * 4 + 3];
            int lsum = c0 + c1 + c2 + c3;
            int pre  = lsum;
            #pragma unroll
            for (int d = 1; d < 32; d <<= 1) {
                int n = __shfl_up_sync(0xFFFFFFFF, pre, d);
                if (tid >= d) pre += n;
            }
            pre -= lsum;
            offs[tid * 4 + 0] = pre;
            offs[tid * 4 + 1] = pre + c0;
            offs[tid * 4 + 2] = pre + c0 + c1;
            offs[tid * 4 + 3] = pre + c0 + c1 + c2;
        }
        __syncthreads();

        g_sorted[(bid << 9) + offs[bkt] + rank] = packed;
        // Visibility to the next kernel launch is guaranteed by stream order.
    }

    // ---- copy share: 8 independent float4 per thread, evict-first ----
    size_t base = (size_t)bid * 4096 + tid;
    float4 r0 = __ldcs(src + base);
    float4 r1 = __ldcs(src + base + 512);
    float4 r2 = __ldcs(src + base + 1024);
    float4 r3 = __ldcs(src + base + 1536);
    float4 r4 = __ldcs(src + base + 2048);
    float4 r5 = __ldcs(src + base + 2560);
    float4 r6 = __ldcs(src + base + 3072);
    float4 r7 = __ldcs(src + base + 3584);
    __stcs(dst + base,        r0);
    __stcs(dst + base + 512,  r1);
    __stcs(dst + base + 1024, r2);
    __stcs(dst + base + 1536, r3);
    __stcs(dst + base + 2048, r4);
    __stcs(dst + base + 2560, r5);
    __stcs(dst + base + 3072, r6);
    __stcs(dst + base + 3584, r7);
}

// ---------------------------------------------------------------------------
// Kernel 2: bucket-ordered scatter-max + zero out[:,:,1].
// tid = (b*S + s)*A + rank. A warp covers 32 consecutive bucket-ordered
// ranks of one (b,s) row -> atomics land in a narrow ascending vocab window
// (DRAM-row friendly). atomicMax result unused -> RED. Non-negative floats:
// int max == float max. Zeroing col 1 is safe: no atomic targets m==1.
// ---------------------------------------------------------------------------
__global__ void __launch_bounds__(512)
pg_scatter_kernel(const float* __restrict__ att, float* __restrict__ out) {
    unsigned tid  = blockIdx.x * blockDim.x + threadIdx.x;  // 0 .. 524287
    unsigned rank = tid & (AA - 1);
    unsigned bs   = tid >> 9;          // b*S + s  (0 .. 1023)
    unsigned b    = bs >> 5;

    if (tid < BB * SS) {
        out[(size_t)tid * VOCAB + 1] = 0.0f;     // out[:, :, 1] = 0
    }

    int packed = g_sorted[(b << 9) | rank];
    if (packed != SENTINEL) {
        int m = packed >> 9;
        int a = packed & (AA - 1);
        float v = att[(size_t)bs * AA + a];
        atomicMax((int*)out + (size_t)bs * VOCAB + m, __float_as_int(v));
    }
}

// ---------------------------------------------------------------------------
// Launch
// Inputs (metadata order):
//   d_in[0] decoder_outputs  f32 [B,S,VOCAB]
//   d_in[1] attention_scores f32 [B,S,A]
//   d_in[2] input_sequence   i32 [B,A]
//   d_in[3] repeat_idx       i32 [S,1]   (unused)
//   d_in[4] repeat_idx2      i32 [B,1]   (unused)
//   d_in[5] convert_table    i32 [SRC_VOCAB]
// Output: f32 [B,S,VOCAB]
// ---------------------------------------------------------------------------
extern "C" void kernel_launch(void* const* d_in, const int* in_sizes, int n_in,
                              void* d_out, int out_size) {
    const float4* dec = (const float4*)d_in[0];
    const float*  att = (const float*)d_in[1];
    const int*    seq = (const int*)d_in[2];
    const int*    tbl = (const int*)d_in[5];
    float*        out = (float*)d_out;

    const int n4 = BB * SS * VOCAB / 4;                 // 8,192,000
    pg_copy_sort_kernel<<<n4 / 4096, 512>>>(dec, (float4*)out, seq, tbl);

    pg_scatter_kernel<<<(BB * SS * AA) / 512, 512>>>(att, out);
}